// round 2
// baseline (speedup 1.0000x reference)
#include <cuda_runtime.h>
#include <math.h>
#include <stdint.h>

// ---------------- problem constants ----------------
#define HID 4096
#define NH  32
#define NKV 8
#define HD  128
#define MAX_NNZ 4096
#define MAX_S   1024

// ---------------- device scratch (no allocs allowed) ----------------
__device__ float g_q   [(size_t)MAX_NNZ * NH  * HD];   // 64MB  Q after proj (+RoPE in-place)
__device__ float g_kt  [(size_t)MAX_NNZ * NKV * HD];   // 16MB  K proj (token order)
__device__ float g_vt  [(size_t)MAX_NNZ * NKV * HD];   // 16MB  V proj (token order)
__device__ float g_kg  [(size_t)MAX_NNZ * NKV * HD];   // 16MB  K gathered [b][pos][kvh][d], RoPE'd
__device__ float g_vg  [(size_t)MAX_NNZ * NKV * HD];   // 16MB  V gathered
__device__ float g_attn[(size_t)MAX_NNZ * NH  * HD];   // 64MB  attention output
__device__ float g_cos [MAX_S * 64];
__device__ float g_sin [MAX_S * 64];

// ---------------- RoPE table (llama 3.1 scaling), double precision ----------------
__global__ void rope_table_kernel() {
    int p = blockIdx.x;
    int j = threadIdx.x;                   // 0..63
    double e    = (double)j / 64.0;        // 2j/head_dim
    double freq = exp(-e * log(500000.0));
    const double PI = 3.14159265358979323846;
    double wavelen = 2.0 * PI / freq;
    double f;
    if (wavelen < 2048.0)       f = freq;            // old_ctx/high_ff
    else if (wavelen > 8192.0)  f = freq / 8.0;      // old_ctx/low_ff
    else {
        double smooth = (8192.0 / wavelen - 1.0) / 3.0;
        f = (1.0 - smooth) * freq / 8.0 + smooth * freq;
    }
    double ang = (double)p * f;
    g_cos[p * 64 + j] = (float)cos(ang);
    g_sin[p * 64 + j] = (float)sin(ang);
}

// ---------------- RoPE on Q (in place) ----------------
__global__ void rope_q_kernel(float* __restrict__ q, const int* __restrict__ pos) {
    int i = blockIdx.x;
    int p = pos[i];
    const float* cr = g_cos + (size_t)p * 64;
    const float* sr = g_sin + (size_t)p * 64;
    float* base = q + (size_t)i * (NH * HD);
    for (int idx = threadIdx.x; idx < NH * 64; idx += blockDim.x) {
        int h = idx >> 6, j = idx & 63;
        float c = cr[j], s = sr[j];
        float* hb = base + h * HD;
        float x1 = hb[j], x2 = hb[j + 64];
        hb[j]      = x1 * c - x2 * s;
        hb[j + 64] = x2 * c + x1 * s;
    }
}

// ---------------- RoPE K + scatter K/V into gathered layout ----------------
// With unique pages, paged scatter->gather composes to: gathered index == position.
__global__ void ropekv_scatter_kernel(const int* __restrict__ pos, int s_per_b) {
    int i = blockIdx.x;
    int b = i / s_per_b;
    int p = pos[i];
    int dst = b * s_per_b + p;
    const float* cr = g_cos + (size_t)p * 64;
    const float* sr = g_sin + (size_t)p * 64;
    const float* kin  = g_kt + (size_t)i   * (NKV * HD);
    float*       kout = g_kg + (size_t)dst * (NKV * HD);
    for (int idx = threadIdx.x; idx < NKV * 64; idx += blockDim.x) {
        int h = idx >> 6, j = idx & 63;
        float c = cr[j], s = sr[j];
        float x1 = kin[h * HD + j], x2 = kin[h * HD + j + 64];
        kout[h * HD + j]      = x1 * c - x2 * s;
        kout[h * HD + j + 64] = x2 * c + x1 * s;
    }
    const float* vin  = g_vt + (size_t)i   * (NKV * HD);
    float*       vout = g_vg + (size_t)dst * (NKV * HD);
    for (int idx = threadIdx.x; idx < NKV * HD; idx += blockDim.x)
        vout[idx] = vin[idx];
}

// ---------------- fp32 SGEMM: C[M,N] = A[M,K] * B[N,K]^T ----------------
// 128x128 block tile, BK=16, 256 threads, 8x8 microtile.
__global__ __launch_bounds__(256, 2)
void sgemm_nt(const float* __restrict__ A, const float* __restrict__ B,
              float* __restrict__ C, int M, int N, int K) {
    __shared__ float As[16][128];
    __shared__ float Bs[16][128];
    int tid = threadIdx.x;
    int m0 = blockIdx.y << 7;
    int n0 = blockIdx.x << 7;
    int tx = tid & 15, ty = tid >> 4;

    float acc[8][8];
#pragma unroll
    for (int i = 0; i < 8; ++i)
#pragma unroll
        for (int j = 0; j < 8; ++j) acc[i][j] = 0.f;

    int lrow = tid >> 2;            // 0..63
    int lq   = (tid & 3) << 2;      // 0,4,8,12
    const float* Ap = A + (size_t)(m0 + lrow) * K + lq;
    const float* Bp = B + (size_t)(n0 + lrow) * K + lq;
    const size_t rstride = (size_t)64 * K;

    for (int k0 = 0; k0 < K; k0 += 16) {
        float4 a1 = *(const float4*)(Ap + k0);
        float4 a2 = *(const float4*)(Ap + rstride + k0);
        float4 b1 = *(const float4*)(Bp + k0);
        float4 b2 = *(const float4*)(Bp + rstride + k0);
        __syncthreads();   // WAR: prior iteration done reading smem
        As[lq + 0][lrow] = a1.x; As[lq + 1][lrow] = a1.y;
        As[lq + 2][lrow] = a1.z; As[lq + 3][lrow] = a1.w;
        As[lq + 0][lrow + 64] = a2.x; As[lq + 1][lrow + 64] = a2.y;
        As[lq + 2][lrow + 64] = a2.z; As[lq + 3][lrow + 64] = a2.w;
        Bs[lq + 0][lrow] = b1.x; Bs[lq + 1][lrow] = b1.y;
        Bs[lq + 2][lrow] = b1.z; Bs[lq + 3][lrow] = b1.w;
        Bs[lq + 0][lrow + 64] = b2.x; Bs[lq + 1][lrow + 64] = b2.y;
        Bs[lq + 2][lrow + 64] = b2.z; Bs[lq + 3][lrow + 64] = b2.w;
        __syncthreads();
#pragma unroll
        for (int k = 0; k < 16; ++k) {
            float a[8], bb[8];
            *(float4*)(a)     = *(const float4*)&As[k][ty * 8];
            *(float4*)(a + 4) = *(const float4*)&As[k][ty * 8 + 4];
            *(float4*)(bb)    = *(const float4*)&Bs[k][tx * 8];
            *(float4*)(bb + 4)= *(const float4*)&Bs[k][tx * 8 + 4];
#pragma unroll
            for (int i = 0; i < 8; ++i)
#pragma unroll
                for (int j = 0; j < 8; ++j)
                    acc[i][j] = fmaf(a[i], bb[j], acc[i][j]);
        }
    }
#pragma unroll
    for (int i = 0; i < 8; ++i) {
        float* cp = C + (size_t)(m0 + ty * 8 + i) * N + n0 + tx * 8;
        *(float4*)cp       = make_float4(acc[i][0], acc[i][1], acc[i][2], acc[i][3]);
        *(float4*)(cp + 4) = make_float4(acc[i][4], acc[i][5], acc[i][6], acc[i][7]);
    }
}

// ---------------- flash attention (fp32, causal, GQA) ----------------
// Block: one (batch, head, 128-row q tile); 256 threads (ty=tid>>3 in 0..31, tx=tid&7).
// Tiles of 64 kv rows. S frag 4x8 (cols = tx+8*jj), O frag 4x16 (cols = tx+8*j).
#define QPITCH 132
#define KPITCH 132
#define VPITCH 68
#define PPITCH 68
__global__ void attn_kernel(const float* __restrict__ Q, const float* __restrict__ K,
                            const float* __restrict__ V, float* __restrict__ O,
                            int S, float scale) {
    extern __shared__ float sm[];
    float* Qs = sm;                          // [128][132]
    float* Ks = Qs + 128 * QPITCH;           // [64][132]
    float* Vt = Ks + 64 * KPITCH;            // [128][68]  (transposed: Vt[d][kv])
    float* Ps = Vt + 128 * VPITCH;           // [128][68]

    int qt = blockIdx.x, h = blockIdx.y, b = blockIdx.z;
    int kvh = h / (NH / NKV);
    int tid = threadIdx.x;
    int tx = tid & 7, ty = tid >> 3;
    int q0 = qt * 128;

    // load Q tile
    for (int it = tid; it < 128 * 32; it += 256) {
        int r = it >> 5, dq = (it & 31) * 4;
        float4 v = *(const float4*)(Q + ((size_t)(b * S + q0 + r) * NH + h) * HD + dq);
        float* dst = &Qs[r * QPITCH + dq];
        dst[0] = v.x; dst[1] = v.y; dst[2] = v.z; dst[3] = v.w;
    }

    float m_i[4], l_i[4], Of[4][16];
#pragma unroll
    for (int i = 0; i < 4; ++i) {
        m_i[i] = -3.0e38f; l_i[i] = 0.f;
#pragma unroll
        for (int j = 0; j < 16; ++j) Of[i][j] = 0.f;
    }

    int ntiles = (q0 + 128) / 64;
    for (int t = 0; t < ntiles; ++t) {
        int kv0 = t * 64;
        __syncthreads();  // prior PV done before overwriting Ks/Vt/Ps
        // load K, V tiles
        for (int it = tid; it < 64 * 32; it += 256) {
            int c = it >> 5, dq = (it & 31) * 4;
            const float* kp = K + ((size_t)(b * S + kv0 + c) * NKV + kvh) * HD + dq;
            float4 kk = *(const float4*)kp;
            float* kd = &Ks[c * KPITCH + dq];
            kd[0] = kk.x; kd[1] = kk.y; kd[2] = kk.z; kd[3] = kk.w;
            const float* vp = V + ((size_t)(b * S + kv0 + c) * NKV + kvh) * HD + dq;
            float4 vv = *(const float4*)vp;
            Vt[(dq + 0) * VPITCH + c] = vv.x;
            Vt[(dq + 1) * VPITCH + c] = vv.y;
            Vt[(dq + 2) * VPITCH + c] = vv.z;
            Vt[(dq + 3) * VPITCH + c] = vv.w;
        }
        __syncthreads();

        // S = Q K^T  (4 rows x 8 cols per thread)
        float acc[4][8];
#pragma unroll
        for (int i = 0; i < 4; ++i)
#pragma unroll
            for (int j = 0; j < 8; ++j) acc[i][j] = 0.f;
#pragma unroll 4
        for (int k4 = 0; k4 < 32; ++k4) {
            float4 qa[4];
#pragma unroll
            for (int i = 0; i < 4; ++i)
                qa[i] = *(const float4*)&Qs[(ty * 4 + i) * QPITCH + k4 * 4];
#pragma unroll
            for (int j = 0; j < 8; ++j) {
                float4 kb = *(const float4*)&Ks[(tx + 8 * j) * KPITCH + k4 * 4];
#pragma unroll
                for (int i = 0; i < 4; ++i)
                    acc[i][j] += qa[i].x * kb.x + qa[i].y * kb.y
                               + qa[i].z * kb.z + qa[i].w * kb.w;
            }
        }

        // mask + online softmax
#pragma unroll
        for (int i = 0; i < 4; ++i) {
            int qi = q0 + ty * 4 + i;
            float mrow = -3.0e38f;
#pragma unroll
            for (int j = 0; j < 8; ++j) {
                int kidx = kv0 + tx + 8 * j;
                float sv = (kidx <= qi) ? acc[i][j] * scale : -1.0e30f;
                acc[i][j] = sv;
                mrow = fmaxf(mrow, sv);
            }
            mrow = fmaxf(mrow, __shfl_xor_sync(0xffffffffu, mrow, 1));
            mrow = fmaxf(mrow, __shfl_xor_sync(0xffffffffu, mrow, 2));
            mrow = fmaxf(mrow, __shfl_xor_sync(0xffffffffu, mrow, 4));
            float mnew  = fmaxf(m_i[i], mrow);
            float alpha = expf(m_i[i] - mnew);
            float lsum = 0.f;
#pragma unroll
            for (int j = 0; j < 8; ++j) {
                float p = expf(acc[i][j] - mnew);
                acc[i][j] = p;
                lsum += p;
            }
            lsum += __shfl_xor_sync(0xffffffffu, lsum, 1);
            lsum += __shfl_xor_sync(0xffffffffu, lsum, 2);
            lsum += __shfl_xor_sync(0xffffffffu, lsum, 4);
            l_i[i] = l_i[i] * alpha + lsum;
            m_i[i] = mnew;
#pragma unroll
            for (int j = 0; j < 16; ++j) Of[i][j] *= alpha;
#pragma unroll
            for (int j = 0; j < 8; ++j)
                Ps[(ty * 4 + i) * PPITCH + tx + 8 * j] = acc[i][j];
        }
        __syncthreads();

        // O += P V   (4 rows x 16 cols per thread)
#pragma unroll 4
        for (int k4 = 0; k4 < 16; ++k4) {
            float4 pa[4];
#pragma unroll
            for (int i = 0; i < 4; ++i)
                pa[i] = *(const float4*)&Ps[(ty * 4 + i) * PPITCH + k4 * 4];
#pragma unroll
            for (int j = 0; j < 16; ++j) {
                float4 vb = *(const float4*)&Vt[(tx + 8 * j) * VPITCH + k4 * 4];
#pragma unroll
                for (int i = 0; i < 4; ++i)
                    Of[i][j] += pa[i].x * vb.x + pa[i].y * vb.y
                              + pa[i].z * vb.z + pa[i].w * vb.w;
            }
        }
    }

    // epilogue
#pragma unroll
    for (int i = 0; i < 4; ++i) {
        int row = q0 + ty * 4 + i;
        float inv = 1.f / l_i[i];
        float* op = O + ((size_t)(b * S + row) * NH + h) * HD;
#pragma unroll
        for (int j = 0; j < 16; ++j)
            op[tx + 8 * j] = Of[i][j] * inv;
    }
}

// ---------------- launch ----------------
extern "C" void kernel_launch(void* const* d_in, const int* in_sizes, int n_in,
                              void* d_out, int out_size) {
    const float* hs  = (const float*)d_in[0];
    const float* wq  = (const float*)d_in[1];
    const float* wk  = (const float*)d_in[2];
    const float* wv  = (const float*)d_in[3];
    const float* wo  = (const float*)d_in[4];
    const int*   pos = (const int*)  d_in[6];

    int nnz = in_sizes[0] / HID;
    int b   = in_sizes[10] - 1;
    int s   = nnz / b;

    float *q, *kt, *vt, *kg, *vg, *attn;
    cudaGetSymbolAddress((void**)&q,    g_q);
    cudaGetSymbolAddress((void**)&kt,   g_kt);
    cudaGetSymbolAddress((void**)&vt,   g_vt);
    cudaGetSymbolAddress((void**)&kg,   g_kg);
    cudaGetSymbolAddress((void**)&vg,   g_vg);
    cudaGetSymbolAddress((void**)&attn, g_attn);

    const size_t ATTN_SMEM =
        (size_t)(128 * QPITCH + 64 * KPITCH + 128 * VPITCH + 128 * PPITCH) * sizeof(float);
    cudaFuncSetAttribute(attn_kernel, cudaFuncAttributeMaxDynamicSharedMemorySize,
                         (int)ATTN_SMEM);

    // 1. RoPE cos/sin table
    rope_table_kernel<<<s, 64>>>();

    // 2. projections (NT GEMMs)
    sgemm_nt<<<dim3((NH * HD) / 128, nnz / 128), 256>>>(hs, wq, q,  nnz, NH * HD,  HID);
    sgemm_nt<<<dim3((NKV * HD) / 128, nnz / 128), 256>>>(hs, wk, kt, nnz, NKV * HD, HID);
    sgemm_nt<<<dim3((NKV * HD) / 128, nnz / 128), 256>>>(hs, wv, vt, nnz, NKV * HD, HID);

    // 3. RoPE + paged-KV scatter (gathered order == position)
    rope_q_kernel<<<nnz, 256>>>(q, pos);
    ropekv_scatter_kernel<<<nnz, 256>>>(pos, s);

    // 4. causal GQA flash attention
    float scale = 1.0f / sqrtf((float)HD);
    attn_kernel<<<dim3(s / 128, NH, b), 256, ATTN_SMEM>>>(q, kg, vg, attn, s, scale);

    // 5. output projection
    sgemm_nt<<<dim3(HID / 128, nnz / 128), 256>>>(attn, wo, (float*)d_out, nnz, HID, NH * HD);
}

// round 3
// speedup vs baseline: 1.0001x; 1.0001x over previous
#include <cuda_runtime.h>
#include <math.h>
#include <stdint.h>

// ---------------- problem constants ----------------
#define HID 4096
#define NH  32
#define NKV 8
#define HD  128
#define MAX_NNZ 4096
#define MAX_S   1024

// ---------------- device scratch (no allocs allowed) ----------------
__device__ float g_q   [(size_t)MAX_NNZ * NH  * HD];   // 64MB  Q after proj (+RoPE in-place)
__device__ float g_kt  [(size_t)MAX_NNZ * NKV * HD];   // 16MB  K proj (token order)
__device__ float g_vt  [(size_t)MAX_NNZ * NKV * HD];   // 16MB  V proj (token order)
__device__ float g_kg  [(size_t)MAX_NNZ * NKV * HD];   // 16MB  K gathered [b][pos][kvh][d], RoPE'd
__device__ float g_vg  [(size_t)MAX_NNZ * NKV * HD];   // 16MB  V gathered
__device__ float g_attn[(size_t)MAX_NNZ * NH  * HD];   // 64MB  attention output
__device__ float g_cos [MAX_S * 64];
__device__ float g_sin [MAX_S * 64];

// ---------------- RoPE table (llama 3.1 scaling), double precision ----------------
__global__ void rope_table_kernel() {
    int p = blockIdx.x;
    int j = threadIdx.x;                   // 0..63
    double e    = (double)j / 64.0;        // 2j/head_dim
    double freq = exp(-e * log(500000.0));
    const double PI = 3.14159265358979323846;
    double wavelen = 2.0 * PI / freq;
    double f;
    if (wavelen < 2048.0)       f = freq;            // old_ctx/high_ff
    else if (wavelen > 8192.0)  f = freq / 8.0;      // old_ctx/low_ff
    else {
        double smooth = (8192.0 / wavelen - 1.0) / 3.0;
        f = (1.0 - smooth) * freq / 8.0 + smooth * freq;
    }
    double ang = (double)p * f;
    g_cos[p * 64 + j] = (float)cos(ang);
    g_sin[p * 64 + j] = (float)sin(ang);
}

// ---------------- RoPE on Q (in place) ----------------
__global__ void rope_q_kernel(float* __restrict__ q, const int* __restrict__ pos) {
    int i = blockIdx.x;
    int p = pos[i];
    const float* cr = g_cos + (size_t)p * 64;
    const float* sr = g_sin + (size_t)p * 64;
    float* base = q + (size_t)i * (NH * HD);
    for (int idx = threadIdx.x; idx < NH * 64; idx += blockDim.x) {
        int h = idx >> 6, j = idx & 63;
        float c = cr[j], s = sr[j];
        float* hb = base + h * HD;
        float x1 = hb[j], x2 = hb[j + 64];
        hb[j]      = x1 * c - x2 * s;
        hb[j + 64] = x2 * c + x1 * s;
    }
}

// ---------------- RoPE K + scatter K/V into gathered layout ----------------
// With unique pages, paged scatter->gather composes to: gathered index == position.
__global__ void ropekv_scatter_kernel(const int* __restrict__ pos, int s_per_b) {
    int i = blockIdx.x;
    int b = i / s_per_b;
    int p = pos[i];
    int dst = b * s_per_b + p;
    const float* cr = g_cos + (size_t)p * 64;
    const float* sr = g_sin + (size_t)p * 64;
    const float* kin  = g_kt + (size_t)i   * (NKV * HD);
    float*       kout = g_kg + (size_t)dst * (NKV * HD);
    for (int idx = threadIdx.x; idx < NKV * 64; idx += blockDim.x) {
        int h = idx >> 6, j = idx & 63;
        float c = cr[j], s = sr[j];
        float x1 = kin[h * HD + j], x2 = kin[h * HD + j + 64];
        kout[h * HD + j]      = x1 * c - x2 * s;
        kout[h * HD + j + 64] = x2 * c + x1 * s;
    }
    const float* vin  = g_vt + (size_t)i   * (NKV * HD);
    float*       vout = g_vg + (size_t)dst * (NKV * HD);
    for (int idx = threadIdx.x; idx < NKV * HD; idx += blockDim.x)
        vout[idx] = vin[idx];
}

// ---------------- fp32 SGEMM: C[M,N] = A[M,K] * B[N,K]^T ----------------
// 128x128 block tile, BK=16, 256 threads, 8x8 microtile.
__global__ __launch_bounds__(256, 2)
void sgemm_nt(const float* __restrict__ A, const float* __restrict__ B,
              float* __restrict__ C, int M, int N, int K) {
    __shared__ float As[16][128];
    __shared__ float Bs[16][128];
    int tid = threadIdx.x;
    int m0 = blockIdx.y << 7;
    int n0 = blockIdx.x << 7;
    int tx = tid & 15, ty = tid >> 4;

    float acc[8][8];
#pragma unroll
    for (int i = 0; i < 8; ++i)
#pragma unroll
        for (int j = 0; j < 8; ++j) acc[i][j] = 0.f;

    int lrow = tid >> 2;            // 0..63
    int lq   = (tid & 3) << 2;      // 0,4,8,12
    const float* Ap = A + (size_t)(m0 + lrow) * K + lq;
    const float* Bp = B + (size_t)(n0 + lrow) * K + lq;
    const size_t rstride = (size_t)64 * K;

    for (int k0 = 0; k0 < K; k0 += 16) {
        float4 a1 = *(const float4*)(Ap + k0);
        float4 a2 = *(const float4*)(Ap + rstride + k0);
        float4 b1 = *(const float4*)(Bp + k0);
        float4 b2 = *(const float4*)(Bp + rstride + k0);
        __syncthreads();   // WAR: prior iteration done reading smem
        As[lq + 0][lrow] = a1.x; As[lq + 1][lrow] = a1.y;
        As[lq + 2][lrow] = a1.z; As[lq + 3][lrow] = a1.w;
        As[lq + 0][lrow + 64] = a2.x; As[lq + 1][lrow + 64] = a2.y;
        As[lq + 2][lrow + 64] = a2.z; As[lq + 3][lrow + 64] = a2.w;
        Bs[lq + 0][lrow] = b1.x; Bs[lq + 1][lrow] = b1.y;
        Bs[lq + 2][lrow] = b1.z; Bs[lq + 3][lrow] = b1.w;
        Bs[lq + 0][lrow + 64] = b2.x; Bs[lq + 1][lrow + 64] = b2.y;
        Bs[lq + 2][lrow + 64] = b2.z; Bs[lq + 3][lrow + 64] = b2.w;
        __syncthreads();
#pragma unroll
        for (int k = 0; k < 16; ++k) {
            float a[8], bb[8];
            *(float4*)(a)     = *(const float4*)&As[k][ty * 8];
            *(float4*)(a + 4) = *(const float4*)&As[k][ty * 8 + 4];
            *(float4*)(bb)    = *(const float4*)&Bs[k][tx * 8];
            *(float4*)(bb + 4)= *(const float4*)&Bs[k][tx * 8 + 4];
#pragma unroll
            for (int i = 0; i < 8; ++i)
#pragma unroll
                for (int j = 0; j < 8; ++j)
                    acc[i][j] = fmaf(a[i], bb[j], acc[i][j]);
        }
    }
#pragma unroll
    for (int i = 0; i < 8; ++i) {
        float* cp = C + (size_t)(m0 + ty * 8 + i) * N + n0 + tx * 8;
        *(float4*)cp       = make_float4(acc[i][0], acc[i][1], acc[i][2], acc[i][3]);
        *(float4*)(cp + 4) = make_float4(acc[i][4], acc[i][5], acc[i][6], acc[i][7]);
    }
}

// ---------------- flash attention (fp32, causal, GQA) ----------------
// Block: one (batch, head, 128-row q tile); 256 threads (ty=tid>>3 in 0..31, tx=tid&7).
// Tiles of 64 kv rows. S frag 4x8 (cols = tx+8*jj), O frag 4x16 (cols = tx+8*j).
#define QPITCH 132
#define KPITCH 132
#define VPITCH 68
#define PPITCH 68
__global__ void attn_kernel(const float* __restrict__ Q, const float* __restrict__ K,
                            const float* __restrict__ V, float* __restrict__ O,
                            int S, float scale) {
    extern __shared__ float sm[];
    float* Qs = sm;                          // [128][132]
    float* Ks = Qs + 128 * QPITCH;           // [64][132]
    float* Vt = Ks + 64 * KPITCH;            // [128][68]  (transposed: Vt[d][kv])
    float* Ps = Vt + 128 * VPITCH;           // [128][68]

    int qt = blockIdx.x, h = blockIdx.y, b = blockIdx.z;
    int kvh = h / (NH / NKV);
    int tid = threadIdx.x;
    int tx = tid & 7, ty = tid >> 3;
    int q0 = qt * 128;

    // load Q tile
    for (int it = tid; it < 128 * 32; it += 256) {
        int r = it >> 5, dq = (it & 31) * 4;
        float4 v = *(const float4*)(Q + ((size_t)(b * S + q0 + r) * NH + h) * HD + dq);
        float* dst = &Qs[r * QPITCH + dq];
        dst[0] = v.x; dst[1] = v.y; dst[2] = v.z; dst[3] = v.w;
    }

    float m_i[4], l_i[4], Of[4][16];
#pragma unroll
    for (int i = 0; i < 4; ++i) {
        m_i[i] = -3.0e38f; l_i[i] = 0.f;
#pragma unroll
        for (int j = 0; j < 16; ++j) Of[i][j] = 0.f;
    }

    int ntiles = (q0 + 128) / 64;
    for (int t = 0; t < ntiles; ++t) {
        int kv0 = t * 64;
        __syncthreads();  // prior PV done before overwriting Ks/Vt/Ps
        // load K, V tiles
        for (int it = tid; it < 64 * 32; it += 256) {
            int c = it >> 5, dq = (it & 31) * 4;
            const float* kp = K + ((size_t)(b * S + kv0 + c) * NKV + kvh) * HD + dq;
            float4 kk = *(const float4*)kp;
            float* kd = &Ks[c * KPITCH + dq];
            kd[0] = kk.x; kd[1] = kk.y; kd[2] = kk.z; kd[3] = kk.w;
            const float* vp = V + ((size_t)(b * S + kv0 + c) * NKV + kvh) * HD + dq;
            float4 vv = *(const float4*)vp;
            Vt[(dq + 0) * VPITCH + c] = vv.x;
            Vt[(dq + 1) * VPITCH + c] = vv.y;
            Vt[(dq + 2) * VPITCH + c] = vv.z;
            Vt[(dq + 3) * VPITCH + c] = vv.w;
        }
        __syncthreads();

        // S = Q K^T  (4 rows x 8 cols per thread)
        float acc[4][8];
#pragma unroll
        for (int i = 0; i < 4; ++i)
#pragma unroll
            for (int j = 0; j < 8; ++j) acc[i][j] = 0.f;
#pragma unroll 4
        for (int k4 = 0; k4 < 32; ++k4) {
            float4 qa[4];
#pragma unroll
            for (int i = 0; i < 4; ++i)
                qa[i] = *(const float4*)&Qs[(ty * 4 + i) * QPITCH + k4 * 4];
#pragma unroll
            for (int j = 0; j < 8; ++j) {
                float4 kb = *(const float4*)&Ks[(tx + 8 * j) * KPITCH + k4 * 4];
#pragma unroll
                for (int i = 0; i < 4; ++i)
                    acc[i][j] += qa[i].x * kb.x + qa[i].y * kb.y
                               + qa[i].z * kb.z + qa[i].w * kb.w;
            }
        }

        // mask + online softmax
#pragma unroll
        for (int i = 0; i < 4; ++i) {
            int qi = q0 + ty * 4 + i;
            float mrow = -3.0e38f;
#pragma unroll
            for (int j = 0; j < 8; ++j) {
                int kidx = kv0 + tx + 8 * j;
                float sv = (kidx <= qi) ? acc[i][j] * scale : -1.0e30f;
                acc[i][j] = sv;
                mrow = fmaxf(mrow, sv);
            }
            mrow = fmaxf(mrow, __shfl_xor_sync(0xffffffffu, mrow, 1));
            mrow = fmaxf(mrow, __shfl_xor_sync(0xffffffffu, mrow, 2));
            mrow = fmaxf(mrow, __shfl_xor_sync(0xffffffffu, mrow, 4));
            float mnew  = fmaxf(m_i[i], mrow);
            float alpha = expf(m_i[i] - mnew);
            float lsum = 0.f;
#pragma unroll
            for (int j = 0; j < 8; ++j) {
                float p = expf(acc[i][j] - mnew);
                acc[i][j] = p;
                lsum += p;
            }
            lsum += __shfl_xor_sync(0xffffffffu, lsum, 1);
            lsum += __shfl_xor_sync(0xffffffffu, lsum, 2);
            lsum += __shfl_xor_sync(0xffffffffu, lsum, 4);
            l_i[i] = l_i[i] * alpha + lsum;
            m_i[i] = mnew;
#pragma unroll
            for (int j = 0; j < 16; ++j) Of[i][j] *= alpha;
#pragma unroll
            for (int j = 0; j < 8; ++j)
                Ps[(ty * 4 + i) * PPITCH + tx + 8 * j] = acc[i][j];
        }
        __syncthreads();

        // O += P V   (4 rows x 16 cols per thread)
#pragma unroll 4
        for (int k4 = 0; k4 < 16; ++k4) {
            float4 pa[4];
#pragma unroll
            for (int i = 0; i < 4; ++i)
                pa[i] = *(const float4*)&Ps[(ty * 4 + i) * PPITCH + k4 * 4];
#pragma unroll
            for (int j = 0; j < 16; ++j) {
                float4 vb = *(const float4*)&Vt[(tx + 8 * j) * VPITCH + k4 * 4];
#pragma unroll
                for (int i = 0; i < 4; ++i)
                    Of[i][j] += pa[i].x * vb.x + pa[i].y * vb.y
                              + pa[i].z * vb.z + pa[i].w * vb.w;
            }
        }
    }

    // epilogue
#pragma unroll
    for (int i = 0; i < 4; ++i) {
        int row = q0 + ty * 4 + i;
        float inv = 1.f / l_i[i];
        float* op = O + ((size_t)(b * S + row) * NH + h) * HD;
#pragma unroll
        for (int j = 0; j < 16; ++j)
            op[tx + 8 * j] = Of[i][j] * inv;
    }
}

// ---------------- launch ----------------
extern "C" void kernel_launch(void* const* d_in, const int* in_sizes, int n_in,
                              void* d_out, int out_size) {
    const float* hs  = (const float*)d_in[0];
    const float* wq  = (const float*)d_in[1];
    const float* wk  = (const float*)d_in[2];
    const float* wv  = (const float*)d_in[3];
    const float* wo  = (const float*)d_in[4];
    const int*   pos = (const int*)  d_in[6];

    int nnz = in_sizes[0] / HID;
    int b   = in_sizes[10] - 1;
    int s   = nnz / b;

    float *q, *kt, *vt, *kg, *vg, *attn;
    cudaGetSymbolAddress((void**)&q,    g_q);
    cudaGetSymbolAddress((void**)&kt,   g_kt);
    cudaGetSymbolAddress((void**)&vt,   g_vt);
    cudaGetSymbolAddress((void**)&kg,   g_kg);
    cudaGetSymbolAddress((void**)&vg,   g_vg);
    cudaGetSymbolAddress((void**)&attn, g_attn);

    const size_t ATTN_SMEM =
        (size_t)(128 * QPITCH + 64 * KPITCH + 128 * VPITCH + 128 * PPITCH) * sizeof(float);
    cudaFuncSetAttribute(attn_kernel, cudaFuncAttributeMaxDynamicSharedMemorySize,
                         (int)ATTN_SMEM);

    // 1. RoPE cos/sin table
    rope_table_kernel<<<s, 64>>>();

    // 2. projections (NT GEMMs)
    sgemm_nt<<<dim3((NH * HD) / 128, nnz / 128), 256>>>(hs, wq, q,  nnz, NH * HD,  HID);
    sgemm_nt<<<dim3((NKV * HD) / 128, nnz / 128), 256>>>(hs, wk, kt, nnz, NKV * HD, HID);
    sgemm_nt<<<dim3((NKV * HD) / 128, nnz / 128), 256>>>(hs, wv, vt, nnz, NKV * HD, HID);

    // 3. RoPE + paged-KV scatter (gathered order == position)
    rope_q_kernel<<<nnz, 256>>>(q, pos);
    ropekv_scatter_kernel<<<nnz, 256>>>(pos, s);

    // 4. causal GQA flash attention
    float scale = 1.0f / sqrtf((float)HD);
    attn_kernel<<<dim3(s / 128, NH, b), 256, ATTN_SMEM>>>(q, kg, vg, attn, s, scale);

    // 5. output projection
    sgemm_nt<<<dim3(HID / 128, nnz / 128), 256>>>(attn, wo, (float*)d_out, nnz, HID, NH * HD);
}

// round 8
// speedup vs baseline: 1.6627x; 1.6626x over previous
#include <cuda_runtime.h>
#include <cuda_bf16.h>
#include <math.h>
#include <stdint.h>

// ---------------- problem constants ----------------
#define HID 4096
#define NH  32
#define NKV 8
#define HD  128
#define MAX_NNZ 4096
#define MAX_S   1024

// ---------------- device scratch (no allocs allowed) ----------------
__device__ float g_q   [(size_t)MAX_NNZ * NH  * HD];   // Q after proj (+RoPE in-place)
__device__ float g_kt  [(size_t)MAX_NNZ * NKV * HD];   // K proj (token order)
__device__ float g_vt  [(size_t)MAX_NNZ * NKV * HD];   // V proj (token order)
__device__ float g_kg  [(size_t)MAX_NNZ * NKV * HD];   // K gathered, RoPE'd
__device__ float g_vg  [(size_t)MAX_NNZ * NKV * HD];   // V gathered
__device__ float g_attn[(size_t)MAX_NNZ * NH  * HD];   // attention output
__device__ float g_cos [MAX_S * 64];
__device__ float g_sin [MAX_S * 64];

// bf16 split operands (hi/lo) for tensor-core GEMMs
__device__ __nv_bfloat16 g_hs_hi[(size_t)MAX_NNZ * HID];
__device__ __nv_bfloat16 g_hs_lo[(size_t)MAX_NNZ * HID];
__device__ __nv_bfloat16 g_wq_hi[(size_t)NH  * HD * HID];
__device__ __nv_bfloat16 g_wq_lo[(size_t)NH  * HD * HID];
__device__ __nv_bfloat16 g_wk_hi[(size_t)NKV * HD * HID];
__device__ __nv_bfloat16 g_wk_lo[(size_t)NKV * HD * HID];
__device__ __nv_bfloat16 g_wv_hi[(size_t)NKV * HD * HID];
__device__ __nv_bfloat16 g_wv_lo[(size_t)NKV * HD * HID];
__device__ __nv_bfloat16 g_wo_hi[(size_t)HID * NH * HD];
__device__ __nv_bfloat16 g_wo_lo[(size_t)HID * NH * HD];
__device__ __nv_bfloat16 g_at_hi[(size_t)MAX_NNZ * NH * HD];
__device__ __nv_bfloat16 g_at_lo[(size_t)MAX_NNZ * NH * HD];

// ---------------- fp32 -> (bf16 hi, bf16 lo) split ----------------
__global__ void cvt_split_kernel(const float* __restrict__ x,
                                 __nv_bfloat16* __restrict__ hi,
                                 __nv_bfloat16* __restrict__ lo, int n4) {
    int i = blockIdx.x * blockDim.x + threadIdx.x;
    if (i >= n4) return;
    float4 v = ((const float4*)x)[i];
    union { __nv_bfloat16 b[4]; uint2 u; } H, L;
    H.b[0] = __float2bfloat16_rn(v.x);
    H.b[1] = __float2bfloat16_rn(v.y);
    H.b[2] = __float2bfloat16_rn(v.z);
    H.b[3] = __float2bfloat16_rn(v.w);
    L.b[0] = __float2bfloat16_rn(v.x - __bfloat162float(H.b[0]));
    L.b[1] = __float2bfloat16_rn(v.y - __bfloat162float(H.b[1]));
    L.b[2] = __float2bfloat16_rn(v.z - __bfloat162float(H.b[2]));
    L.b[3] = __float2bfloat16_rn(v.w - __bfloat162float(H.b[3]));
    ((uint2*)hi)[i] = H.u;
    ((uint2*)lo)[i] = L.u;
}

// ---------------- RoPE table (llama 3.1 scaling), double precision ----------------
__global__ void rope_table_kernel() {
    int p = blockIdx.x;
    int j = threadIdx.x;                   // 0..63
    double e    = (double)j / 64.0;
    double freq = exp(-e * log(500000.0));
    const double PI = 3.14159265358979323846;
    double wavelen = 2.0 * PI / freq;
    double f;
    if (wavelen < 2048.0)       f = freq;
    else if (wavelen > 8192.0)  f = freq / 8.0;
    else {
        double smooth = (8192.0 / wavelen - 1.0) / 3.0;
        f = (1.0 - smooth) * freq / 8.0 + smooth * freq;
    }
    double ang = (double)p * f;
    g_cos[p * 64 + j] = (float)cos(ang);
    g_sin[p * 64 + j] = (float)sin(ang);
}

// ---------------- RoPE on Q (in place) ----------------
__global__ void rope_q_kernel(float* __restrict__ q, const int* __restrict__ pos) {
    int i = blockIdx.x;
    int p = pos[i];
    const float* cr = g_cos + (size_t)p * 64;
    const float* sr = g_sin + (size_t)p * 64;
    float* base = q + (size_t)i * (NH * HD);
    for (int idx = threadIdx.x; idx < NH * 64; idx += blockDim.x) {
        int h = idx >> 6, j = idx & 63;
        float c = cr[j], s = sr[j];
        float* hb = base + h * HD;
        float x1 = hb[j], x2 = hb[j + 64];
        hb[j]      = x1 * c - x2 * s;
        hb[j + 64] = x2 * c + x1 * s;
    }
}

// ---------------- RoPE K + scatter K/V into gathered layout ----------------
__global__ void ropekv_scatter_kernel(const int* __restrict__ pos, int s_per_b) {
    int i = blockIdx.x;
    int b = i / s_per_b;
    int p = pos[i];
    int dst = b * s_per_b + p;
    const float* cr = g_cos + (size_t)p * 64;
    const float* sr = g_sin + (size_t)p * 64;
    const float* kin  = g_kt + (size_t)i   * (NKV * HD);
    float*       kout = g_kg + (size_t)dst * (NKV * HD);
    for (int idx = threadIdx.x; idx < NKV * 64; idx += blockDim.x) {
        int h = idx >> 6, j = idx & 63;
        float c = cr[j], s = sr[j];
        float x1 = kin[h * HD + j], x2 = kin[h * HD + j + 64];
        kout[h * HD + j]      = x1 * c - x2 * s;
        kout[h * HD + j + 64] = x2 * c + x1 * s;
    }
    const float* vin  = g_vt + (size_t)i   * (NKV * HD);
    float*       vout = g_vg + (size_t)dst * (NKV * HD);
    for (int idx = threadIdx.x; idx < NKV * HD; idx += blockDim.x)
        vout[idx] = vin[idx];
}

// ---------------- bf16 split-MMA GEMM: C[M,N] = A[M,K] * B[N,K]^T ----------------
// 3xBF16 compensation: ab = ahi*bhi + ahi*blo + alo*bhi  (error ~2^-18)
// 128x128 block tile, BK=32 (two k16 MMA steps), 256 threads = 8 warps (4m x 2n),
// warp tile 32x64 = 2 x 8 m16n8k16 fragments.
#define SAPITCH 40   // bf16 elements per smem row (32 data + 8 pad): conflict-free

__device__ __forceinline__ void mma16816(float* c, const uint32_t* a, const uint32_t* b) {
    asm volatile(
        "mma.sync.aligned.m16n8k16.row.col.f32.bf16.bf16.f32 "
        "{%0,%1,%2,%3}, {%4,%5,%6,%7}, {%8,%9}, {%0,%1,%2,%3};\n"
        : "+f"(c[0]), "+f"(c[1]), "+f"(c[2]), "+f"(c[3])
        : "r"(a[0]), "r"(a[1]), "r"(a[2]), "r"(a[3]), "r"(b[0]), "r"(b[1]));
}

__global__ __launch_bounds__(256)
void bgemm_nt(const __nv_bfloat16* __restrict__ Ahi, const __nv_bfloat16* __restrict__ Alo,
              const __nv_bfloat16* __restrict__ Bhi, const __nv_bfloat16* __restrict__ Blo,
              float* __restrict__ C, int M, int N, int K) {
    __shared__ __nv_bfloat16 sAh[128][SAPITCH];
    __shared__ __nv_bfloat16 sAl[128][SAPITCH];
    __shared__ __nv_bfloat16 sBh[128][SAPITCH];
    __shared__ __nv_bfloat16 sBl[128][SAPITCH];

    const int tid = threadIdx.x;
    const int m0 = blockIdx.y << 7;
    const int n0 = blockIdx.x << 7;

    // loader mapping: 8 bf16 (16B) per thread per row; rows r and r+64
    const int lr = tid >> 2;          // 0..63
    const int lc = (tid & 3) << 3;    // 0,8,16,24 (bf16 elems)

    // mma mapping
    const int warp = tid >> 5;
    const int wm = (warp & 3) << 5;   // 0,32,64,96
    const int wn = (warp >> 2) << 6;  // 0,64
    const int lane = tid & 31;
    const int gid = lane >> 2;
    const int tig = lane & 3;

    float acc[2][8][4];
#pragma unroll
    for (int mi = 0; mi < 2; ++mi)
#pragma unroll
        for (int ni = 0; ni < 8; ++ni)
#pragma unroll
            for (int r = 0; r < 4; ++r) acc[mi][ni][r] = 0.f;

    const size_t rowA  = (size_t)(m0 + lr) * K;
    const size_t rowA2 = (size_t)(m0 + lr + 64) * K;
    const size_t rowB  = (size_t)(n0 + lr) * K;
    const size_t rowB2 = (size_t)(n0 + lr + 64) * K;

    for (int k0 = 0; k0 < K; k0 += 32) {
        uint4 ah1 = *(const uint4*)(Ahi + rowA  + k0 + lc);
        uint4 ah2 = *(const uint4*)(Ahi + rowA2 + k0 + lc);
        uint4 al1 = *(const uint4*)(Alo + rowA  + k0 + lc);
        uint4 al2 = *(const uint4*)(Alo + rowA2 + k0 + lc);
        uint4 bh1 = *(const uint4*)(Bhi + rowB  + k0 + lc);
        uint4 bh2 = *(const uint4*)(Bhi + rowB2 + k0 + lc);
        uint4 bl1 = *(const uint4*)(Blo + rowB  + k0 + lc);
        uint4 bl2 = *(const uint4*)(Blo + rowB2 + k0 + lc);
        __syncthreads();   // prior iteration done reading smem
        *(uint4*)&sAh[lr     ][lc] = ah1;
        *(uint4*)&sAh[lr + 64][lc] = ah2;
        *(uint4*)&sAl[lr     ][lc] = al1;
        *(uint4*)&sAl[lr + 64][lc] = al2;
        *(uint4*)&sBh[lr     ][lc] = bh1;
        *(uint4*)&sBh[lr + 64][lc] = bh2;
        *(uint4*)&sBl[lr     ][lc] = bl1;
        *(uint4*)&sBl[lr + 64][lc] = bl2;
        __syncthreads();

#pragma unroll
        for (int ks = 0; ks < 2; ++ks) {
            const int kk = ks * 16 + 2 * tig;
            uint32_t afh[2][4], afl[2][4];
#pragma unroll
            for (int mi = 0; mi < 2; ++mi) {
                const int ra = wm + mi * 16 + gid;
                afh[mi][0] = *(const uint32_t*)&sAh[ra    ][kk];
                afh[mi][1] = *(const uint32_t*)&sAh[ra + 8][kk];
                afh[mi][2] = *(const uint32_t*)&sAh[ra    ][kk + 8];
                afh[mi][3] = *(const uint32_t*)&sAh[ra + 8][kk + 8];
                afl[mi][0] = *(const uint32_t*)&sAl[ra    ][kk];
                afl[mi][1] = *(const uint32_t*)&sAl[ra + 8][kk];
                afl[mi][2] = *(const uint32_t*)&sAl[ra    ][kk + 8];
                afl[mi][3] = *(const uint32_t*)&sAl[ra + 8][kk + 8];
            }
#pragma unroll
            for (int ni = 0; ni < 8; ++ni) {
                const int rb = wn + ni * 8 + gid;
                uint32_t bfh[2], bfl[2];
                bfh[0] = *(const uint32_t*)&sBh[rb][kk];
                bfh[1] = *(const uint32_t*)&sBh[rb][kk + 8];
                bfl[0] = *(const uint32_t*)&sBl[rb][kk];
                bfl[1] = *(const uint32_t*)&sBl[rb][kk + 8];
#pragma unroll
                for (int mi = 0; mi < 2; ++mi) {
                    mma16816(acc[mi][ni], afh[mi], bfh);
                    mma16816(acc[mi][ni], afh[mi], bfl);
                    mma16816(acc[mi][ni], afl[mi], bfh);
                }
            }
        }
    }

    // epilogue
#pragma unroll
    for (int mi = 0; mi < 2; ++mi) {
#pragma unroll
        for (int ni = 0; ni < 8; ++ni) {
            const int row = m0 + wm + mi * 16 + gid;
            const int col = n0 + wn + ni * 8 + 2 * tig;
            *(float2*)&C[(size_t)row * N + col] =
                make_float2(acc[mi][ni][0], acc[mi][ni][1]);
            *(float2*)&C[(size_t)(row + 8) * N + col] =
                make_float2(acc[mi][ni][2], acc[mi][ni][3]);
        }
    }
}

// ---------------- flash attention (fp32, causal, GQA) ----------------
#define QPITCH 132
#define KPITCH 132
#define VPITCH 68
#define PPITCH 68
__global__ void attn_kernel(const float* __restrict__ Q, const float* __restrict__ K,
                            const float* __restrict__ V, float* __restrict__ O,
                            int S, float scale) {
    extern __shared__ float sm[];
    float* Qs = sm;                          // [128][132]
    float* Ks = Qs + 128 * QPITCH;           // [64][132]
    float* Vt = Ks + 64 * KPITCH;            // [128][68]  (transposed: Vt[d][kv])
    float* Ps = Vt + 128 * VPITCH;           // [128][68]

    int qt = blockIdx.x, h = blockIdx.y, b = blockIdx.z;
    int kvh = h / (NH / NKV);
    int tid = threadIdx.x;
    int tx = tid & 7, ty = tid >> 3;
    int q0 = qt * 128;

    for (int it = tid; it < 128 * 32; it += 256) {
        int r = it >> 5, dq = (it & 31) * 4;
        float4 v = *(const float4*)(Q + ((size_t)(b * S + q0 + r) * NH + h) * HD + dq);
        float* dst = &Qs[r * QPITCH + dq];
        dst[0] = v.x; dst[1] = v.y; dst[2] = v.z; dst[3] = v.w;
    }

    float m_i[4], l_i[4], Of[4][16];
#pragma unroll
    for (int i = 0; i < 4; ++i) {
        m_i[i] = -3.0e38f; l_i[i] = 0.f;
#pragma unroll
        for (int j = 0; j < 16; ++j) Of[i][j] = 0.f;
    }

    int ntiles = (q0 + 128) / 64;
    for (int t = 0; t < ntiles; ++t) {
        int kv0 = t * 64;
        __syncthreads();
        for (int it = tid; it < 64 * 32; it += 256) {
            int c = it >> 5, dq = (it & 31) * 4;
            const float* kp = K + ((size_t)(b * S + kv0 + c) * NKV + kvh) * HD + dq;
            float4 kk = *(const float4*)kp;
            float* kd = &Ks[c * KPITCH + dq];
            kd[0] = kk.x; kd[1] = kk.y; kd[2] = kk.z; kd[3] = kk.w;
            const float* vp = V + ((size_t)(b * S + kv0 + c) * NKV + kvh) * HD + dq;
            float4 vv = *(const float4*)vp;
            Vt[(dq + 0) * VPITCH + c] = vv.x;
            Vt[(dq + 1) * VPITCH + c] = vv.y;
            Vt[(dq + 2) * VPITCH + c] = vv.z;
            Vt[(dq + 3) * VPITCH + c] = vv.w;
        }
        __syncthreads();

        float acc[4][8];
#pragma unroll
        for (int i = 0; i < 4; ++i)
#pragma unroll
            for (int j = 0; j < 8; ++j) acc[i][j] = 0.f;
#pragma unroll 4
        for (int k4 = 0; k4 < 32; ++k4) {
            float4 qa[4];
#pragma unroll
            for (int i = 0; i < 4; ++i)
                qa[i] = *(const float4*)&Qs[(ty * 4 + i) * QPITCH + k4 * 4];
#pragma unroll
            for (int j = 0; j < 8; ++j) {
                float4 kb = *(const float4*)&Ks[(tx + 8 * j) * KPITCH + k4 * 4];
#pragma unroll
                for (int i = 0; i < 4; ++i)
                    acc[i][j] += qa[i].x * kb.x + qa[i].y * kb.y
                               + qa[i].z * kb.z + qa[i].w * kb.w;
            }
        }

#pragma unroll
        for (int i = 0; i < 4; ++i) {
            int qi = q0 + ty * 4 + i;
            float mrow = -3.0e38f;
#pragma unroll
            for (int j = 0; j < 8; ++j) {
                int kidx = kv0 + tx + 8 * j;
                float sv = (kidx <= qi) ? acc[i][j] * scale : -1.0e30f;
                acc[i][j] = sv;
                mrow = fmaxf(mrow, sv);
            }
            mrow = fmaxf(mrow, __shfl_xor_sync(0xffffffffu, mrow, 1));
            mrow = fmaxf(mrow, __shfl_xor_sync(0xffffffffu, mrow, 2));
            mrow = fmaxf(mrow, __shfl_xor_sync(0xffffffffu, mrow, 4));
            float mnew  = fmaxf(m_i[i], mrow);
            float alpha = expf(m_i[i] - mnew);
            float lsum = 0.f;
#pragma unroll
            for (int j = 0; j < 8; ++j) {
                float p = expf(acc[i][j] - mnew);
                acc[i][j] = p;
                lsum += p;
            }
            lsum += __shfl_xor_sync(0xffffffffu, lsum, 1);
            lsum += __shfl_xor_sync(0xffffffffu, lsum, 2);
            lsum += __shfl_xor_sync(0xffffffffu, lsum, 4);
            l_i[i] = l_i[i] * alpha + lsum;
            m_i[i] = mnew;
#pragma unroll
            for (int j = 0; j < 16; ++j) Of[i][j] *= alpha;
#pragma unroll
            for (int j = 0; j < 8; ++j)
                Ps[(ty * 4 + i) * PPITCH + tx + 8 * j] = acc[i][j];
        }
        __syncthreads();

#pragma unroll 4
        for (int k4 = 0; k4 < 16; ++k4) {
            float4 pa[4];
#pragma unroll
            for (int i = 0; i < 4; ++i)
                pa[i] = *(const float4*)&Ps[(ty * 4 + i) * PPITCH + k4 * 4];
#pragma unroll
            for (int j = 0; j < 16; ++j) {
                float4 vb = *(const float4*)&Vt[(tx + 8 * j) * VPITCH + k4 * 4];
#pragma unroll
                for (int i = 0; i < 4; ++i)
                    Of[i][j] += pa[i].x * vb.x + pa[i].y * vb.y
                              + pa[i].z * vb.z + pa[i].w * vb.w;
            }
        }
    }

#pragma unroll
    for (int i = 0; i < 4; ++i) {
        int row = q0 + ty * 4 + i;
        float inv = 1.f / l_i[i];
        float* op = O + ((size_t)(b * S + row) * NH + h) * HD;
#pragma unroll
        for (int j = 0; j < 16; ++j)
            op[tx + 8 * j] = Of[i][j] * inv;
    }
}

// ---------------- launch ----------------
extern "C" void kernel_launch(void* const* d_in, const int* in_sizes, int n_in,
                              void* d_out, int out_size) {
    const float* hs  = (const float*)d_in[0];
    const float* wq  = (const float*)d_in[1];
    const float* wk  = (const float*)d_in[2];
    const float* wv  = (const float*)d_in[3];
    const float* wo  = (const float*)d_in[4];
    const int*   pos = (const int*)  d_in[6];

    int nnz = in_sizes[0] / HID;
    int b   = in_sizes[10] - 1;
    int s   = nnz / b;

    float *q, *kt, *vt, *kg, *vg, *attn;
    cudaGetSymbolAddress((void**)&q,    g_q);
    cudaGetSymbolAddress((void**)&kt,   g_kt);
    cudaGetSymbolAddress((void**)&vt,   g_vt);
    cudaGetSymbolAddress((void**)&kg,   g_kg);
    cudaGetSymbolAddress((void**)&vg,   g_vg);
    cudaGetSymbolAddress((void**)&attn, g_attn);

    __nv_bfloat16 *hsh, *hsl, *wqh, *wql, *wkh, *wkl, *wvh, *wvl, *woh, *wol, *ath, *atl;
    cudaGetSymbolAddress((void**)&hsh, g_hs_hi);
    cudaGetSymbolAddress((void**)&hsl, g_hs_lo);
    cudaGetSymbolAddress((void**)&wqh, g_wq_hi);
    cudaGetSymbolAddress((void**)&wql, g_wq_lo);
    cudaGetSymbolAddress((void**)&wkh, g_wk_hi);
    cudaGetSymbolAddress((void**)&wkl, g_wk_lo);
    cudaGetSymbolAddress((void**)&wvh, g_wv_hi);
    cudaGetSymbolAddress((void**)&wvl, g_wv_lo);
    cudaGetSymbolAddress((void**)&woh, g_wo_hi);
    cudaGetSymbolAddress((void**)&wol, g_wo_lo);
    cudaGetSymbolAddress((void**)&ath, g_at_hi);
    cudaGetSymbolAddress((void**)&atl, g_at_lo);

    const size_t ATTN_SMEM =
        (size_t)(128 * QPITCH + 64 * KPITCH + 128 * VPITCH + 128 * PPITCH) * sizeof(float);
    cudaFuncSetAttribute(attn_kernel, cudaFuncAttributeMaxDynamicSharedMemorySize,
                         (int)ATTN_SMEM);

    // 1. RoPE cos/sin table
    rope_table_kernel<<<s, 64>>>();

    // 2. split-convert activations + weights to (bf16 hi, bf16 lo)
    {
        int n4;
        n4 = nnz * HID / 4;          cvt_split_kernel<<<(n4 + 255) / 256, 256>>>(hs, hsh, hsl, n4);
        n4 = NH  * HD * HID / 4;     cvt_split_kernel<<<(n4 + 255) / 256, 256>>>(wq, wqh, wql, n4);
        n4 = NKV * HD * HID / 4;     cvt_split_kernel<<<(n4 + 255) / 256, 256>>>(wk, wkh, wkl, n4);
        n4 = NKV * HD * HID / 4;     cvt_split_kernel<<<(n4 + 255) / 256, 256>>>(wv, wvh, wvl, n4);
        n4 = HID * NH * HD / 4;      cvt_split_kernel<<<(n4 + 255) / 256, 256>>>(wo, woh, wol, n4);
    }

    // 3. projections on the tensor pipe (3xBF16 split NT GEMMs)
    bgemm_nt<<<dim3((NH * HD) / 128, nnz / 128), 256>>>(hsh, hsl, wqh, wql, q,  nnz, NH * HD,  HID);
    bgemm_nt<<<dim3((NKV * HD) / 128, nnz / 128), 256>>>(hsh, hsl, wkh, wkl, kt, nnz, NKV * HD, HID);
    bgemm_nt<<<dim3((NKV * HD) / 128, nnz / 128), 256>>>(hsh, hsl, wvh, wvl, vt, nnz, NKV * HD, HID);

    // 4. RoPE + paged-KV scatter (gathered order == position)
    rope_q_kernel<<<nnz, 256>>>(q, pos);
    ropekv_scatter_kernel<<<nnz, 256>>>(pos, s);

    // 5. causal GQA flash attention (fp32)
    float scale = 1.0f / sqrtf((float)HD);
    attn_kernel<<<dim3(s / 128, NH, b), 256, ATTN_SMEM>>>(q, kg, vg, attn, s, scale);

    // 6. output projection (split attn output, then tensor-pipe GEMM)
    {
        int n4 = nnz * NH * HD / 4;
        cvt_split_kernel<<<(n4 + 255) / 256, 256>>>(attn, ath, atl, n4);
    }
    bgemm_nt<<<dim3(HID / 128, nnz / 128), 256>>>(ath, atl, woh, wol, (float*)d_out, nnz, HID, NH * HD);
}

// round 10
// speedup vs baseline: 2.5063x; 1.5073x over previous
#include <cuda_runtime.h>
#include <cuda_bf16.h>
#include <math.h>
#include <stdint.h>

// ---------------- problem constants ----------------
#define HID 4096
#define NH  32
#define NKV 8
#define HD  128
#define MAX_NNZ 4096
#define MAX_S   1024

// ---------------- device scratch (no allocs allowed) ----------------
__device__ float g_q   [(size_t)MAX_NNZ * NH  * HD];
__device__ float g_kt  [(size_t)MAX_NNZ * NKV * HD];
__device__ float g_vt  [(size_t)MAX_NNZ * NKV * HD];
__device__ float g_kg  [(size_t)MAX_NNZ * NKV * HD];
__device__ float g_vg  [(size_t)MAX_NNZ * NKV * HD];
__device__ float g_attn[(size_t)MAX_NNZ * NH  * HD];
__device__ float g_cos [MAX_S * 64];
__device__ float g_sin [MAX_S * 64];

__device__ __nv_bfloat16 g_hs_hi[(size_t)MAX_NNZ * HID];
__device__ __nv_bfloat16 g_hs_lo[(size_t)MAX_NNZ * HID];
__device__ __nv_bfloat16 g_wq_hi[(size_t)NH  * HD * HID];
__device__ __nv_bfloat16 g_wq_lo[(size_t)NH  * HD * HID];
__device__ __nv_bfloat16 g_wk_hi[(size_t)NKV * HD * HID];
__device__ __nv_bfloat16 g_wk_lo[(size_t)NKV * HD * HID];
__device__ __nv_bfloat16 g_wv_hi[(size_t)NKV * HD * HID];
__device__ __nv_bfloat16 g_wv_lo[(size_t)NKV * HD * HID];
__device__ __nv_bfloat16 g_wo_hi[(size_t)HID * NH * HD];
__device__ __nv_bfloat16 g_wo_lo[(size_t)HID * NH * HD];
__device__ __nv_bfloat16 g_at_hi[(size_t)MAX_NNZ * NH * HD];
__device__ __nv_bfloat16 g_at_lo[(size_t)MAX_NNZ * NH * HD];

// ---------------- helpers ----------------
__device__ __forceinline__ uint32_t smem_u32(const void* p) {
    uint32_t a;
    asm("{ .reg .u64 t; cvta.to.shared.u64 t, %1; cvt.u32.u64 %0, t; }" : "=r"(a) : "l"(p));
    return a;
}
#define SWZ128(o) ((o) ^ (((o) >> 3) & 0x70))

__device__ __forceinline__ void mma16816(float* c, const uint32_t* a, const uint32_t* b) {
    asm volatile(
        "mma.sync.aligned.m16n8k16.row.col.f32.bf16.bf16.f32 "
        "{%0,%1,%2,%3}, {%4,%5,%6,%7}, {%8,%9}, {%0,%1,%2,%3};\n"
        : "+f"(c[0]), "+f"(c[1]), "+f"(c[2]), "+f"(c[3])
        : "r"(a[0]), "r"(a[1]), "r"(a[2]), "r"(a[3]), "r"(b[0]), "r"(b[1]));
}
__device__ __forceinline__ void ldsm4(uint32_t* r, uint32_t addr) {
    asm volatile("ldmatrix.sync.aligned.m8n8.x4.shared.b16 {%0,%1,%2,%3}, [%4];"
        : "=r"(r[0]), "=r"(r[1]), "=r"(r[2]), "=r"(r[3]) : "r"(addr));
}
__device__ __forceinline__ void cp16(uint32_t dst, const void* src) {
    asm volatile("cp.async.cg.shared.global [%0], [%1], 16;" :: "r"(dst), "l"(src));
}

// ---------------- fp32 -> (bf16 hi, bf16 lo) split ----------------
__global__ void cvt_split_kernel(const float* __restrict__ x,
                                 __nv_bfloat16* __restrict__ hi,
                                 __nv_bfloat16* __restrict__ lo, int n4) {
    int i = blockIdx.x * blockDim.x + threadIdx.x;
    if (i >= n4) return;
    float4 v = ((const float4*)x)[i];
    union { __nv_bfloat16 b[4]; uint2 u; } H, L;
    H.b[0] = __float2bfloat16_rn(v.x);
    H.b[1] = __float2bfloat16_rn(v.y);
    H.b[2] = __float2bfloat16_rn(v.z);
    H.b[3] = __float2bfloat16_rn(v.w);
    L.b[0] = __float2bfloat16_rn(v.x - __bfloat162float(H.b[0]));
    L.b[1] = __float2bfloat16_rn(v.y - __bfloat162float(H.b[1]));
    L.b[2] = __float2bfloat16_rn(v.z - __bfloat162float(H.b[2]));
    L.b[3] = __float2bfloat16_rn(v.w - __bfloat162float(H.b[3]));
    ((uint2*)hi)[i] = H.u;
    ((uint2*)lo)[i] = L.u;
}

// ---------------- RoPE table ----------------
__global__ void rope_table_kernel() {
    int p = blockIdx.x;
    int j = threadIdx.x;
    double e    = (double)j / 64.0;
    double freq = exp(-e * log(500000.0));
    const double PI = 3.14159265358979323846;
    double wavelen = 2.0 * PI / freq;
    double f;
    if (wavelen < 2048.0)       f = freq;
    else if (wavelen > 8192.0)  f = freq / 8.0;
    else {
        double smooth = (8192.0 / wavelen - 1.0) / 3.0;
        f = (1.0 - smooth) * freq / 8.0 + smooth * freq;
    }
    double ang = (double)p * f;
    g_cos[p * 64 + j] = (float)cos(ang);
    g_sin[p * 64 + j] = (float)sin(ang);
}

__global__ void rope_q_kernel(float* __restrict__ q, const int* __restrict__ pos) {
    int i = blockIdx.x;
    int p = pos[i];
    const float* cr = g_cos + (size_t)p * 64;
    const float* sr = g_sin + (size_t)p * 64;
    float* base = q + (size_t)i * (NH * HD);
    for (int idx = threadIdx.x; idx < NH * 64; idx += blockDim.x) {
        int h = idx >> 6, j = idx & 63;
        float c = cr[j], s = sr[j];
        float* hb = base + h * HD;
        float x1 = hb[j], x2 = hb[j + 64];
        hb[j]      = x1 * c - x2 * s;
        hb[j + 64] = x2 * c + x1 * s;
    }
}

__global__ void ropekv_scatter_kernel(const int* __restrict__ pos, int s_per_b) {
    int i = blockIdx.x;
    int b = i / s_per_b;
    int p = pos[i];
    int dst = b * s_per_b + p;
    const float* cr = g_cos + (size_t)p * 64;
    const float* sr = g_sin + (size_t)p * 64;
    const float* kin  = g_kt + (size_t)i   * (NKV * HD);
    float*       kout = g_kg + (size_t)dst * (NKV * HD);
    for (int idx = threadIdx.x; idx < NKV * 64; idx += blockDim.x) {
        int h = idx >> 6, j = idx & 63;
        float c = cr[j], s = sr[j];
        float x1 = kin[h * HD + j], x2 = kin[h * HD + j + 64];
        kout[h * HD + j]      = x1 * c - x2 * s;
        kout[h * HD + j + 64] = x2 * c + x1 * s;
    }
    const float* vin  = g_vt + (size_t)i   * (NKV * HD);
    float*       vout = g_vg + (size_t)dst * (NKV * HD);
    for (int idx = threadIdx.x; idx < NKV * HD; idx += blockDim.x)
        vout[idx] = vin[idx];
}

// ================= optimized HMMA split-bf16 GEMM =================
// C[M,N] = A[M,K] * B[N,K]^T via 3xBF16 compensation (hh + hl + lh).
// BM=128, BN=128, BK=64. 256 threads = 8 warps (4m x 2n), warp tile 32x64.
// 2-stage cp.async pipeline, SW128-swizzled smem, ldmatrix fragment loads.
#define BM 128
#define BN 128
#define BK 64
#define ST_BYTES  (64 * 1024)
#define OFF_AH    0
#define OFF_AL    (16 * 1024)
#define OFF_BH    (32 * 1024)
#define OFF_BL    (48 * 1024)
#define GEMM_SMEM (2 * ST_BYTES)

__global__ __launch_bounds__(256, 1)
void hgemm_nt(const __nv_bfloat16* __restrict__ Ahi, const __nv_bfloat16* __restrict__ Alo,
              const __nv_bfloat16* __restrict__ Bhi, const __nv_bfloat16* __restrict__ Blo,
              float* __restrict__ C, int M, int N, int K) {
    extern __shared__ char smc[];
    const uint32_t smb = smem_u32(smc);
    const int tid  = threadIdx.x;
    const int wid  = tid >> 5;
    const int lane = tid & 31;
    const int m0 = blockIdx.y * BM;
    const int n0 = blockIdx.x * BN;
    const int wm = (wid & 3) << 5;    // 0,32,64,96
    const int wn = (wid >> 2) << 6;   // 0,64

    // ldmatrix per-lane fragment rows
    const int a_row0 = wm + (lane & 15);                    // +mi*16
    const int a_csel = lane >> 4;                           // chunk +0/1
    const int b_row0 = wn + (lane & 7) + ((lane >> 4) << 3);// +ni2*16
    const int b_csel = (lane >> 3) & 1;

    // stage loader: each array 128 rows x 8 chunks(16B); 4 chunks/thread/array
    auto load_stage = [&](int st, int k0) {
        const uint32_t sb = smb + st * ST_BYTES;
#pragma unroll
        for (int i = 0; i < 4; ++i) {
            int idx = tid + i * 256;
            int r = idx >> 3, c = idx & 7;
            uint32_t off = SWZ128((uint32_t)(r * 128 + c * 16));
            const size_t ga = (size_t)(m0 + r) * K + k0 + c * 8;
            cp16(sb + OFF_AH + off, Ahi + ga);
            cp16(sb + OFF_AL + off, Alo + ga);
            const size_t gb = (size_t)(n0 + r) * K + k0 + c * 8;
            cp16(sb + OFF_BH + off, Bhi + gb);
            cp16(sb + OFF_BL + off, Blo + gb);
        }
        asm volatile("cp.async.commit_group;" ::: "memory");
    };

    float acc[2][8][4];
#pragma unroll
    for (int mi = 0; mi < 2; ++mi)
#pragma unroll
        for (int ni = 0; ni < 8; ++ni)
#pragma unroll
            for (int r = 0; r < 4; ++r) acc[mi][ni][r] = 0.f;

    load_stage(0, 0);

    const int NIT = K / BK;
    for (int it = 0; it < NIT; ++it) {
        const int cur = it & 1;
        if (it + 1 < NIT) {
            load_stage(cur ^ 1, (it + 1) * BK);
            asm volatile("cp.async.wait_group 1;" ::: "memory");
        } else {
            asm volatile("cp.async.wait_group 0;" ::: "memory");
        }
        __syncthreads();

        const uint32_t sb = smb + cur * ST_BYTES;
#pragma unroll
        for (int ks = 0; ks < 4; ++ks) {
            const int kc = ks * 2;
            uint32_t ah[2][4], al[2][4], bh[4][4], bl[4][4];
#pragma unroll
            for (int mi = 0; mi < 2; ++mi) {
                uint32_t off = SWZ128((uint32_t)((a_row0 + mi * 16) * 128 + (kc + a_csel) * 16));
                ldsm4(ah[mi], sb + OFF_AH + off);
                ldsm4(al[mi], sb + OFF_AL + off);
            }
#pragma unroll
            for (int ni2 = 0; ni2 < 4; ++ni2) {
                uint32_t off = SWZ128((uint32_t)((b_row0 + ni2 * 16) * 128 + (kc + b_csel) * 16));
                ldsm4(bh[ni2], sb + OFF_BH + off);
                ldsm4(bl[ni2], sb + OFF_BL + off);
            }
            // split-outermost ordering: same accumulator reused every 16 MMAs
#pragma unroll
            for (int ni = 0; ni < 8; ++ni)
#pragma unroll
                for (int mi = 0; mi < 2; ++mi)
                    mma16816(acc[mi][ni], ah[mi], &bh[ni >> 1][(ni & 1) * 2]);
#pragma unroll
            for (int ni = 0; ni < 8; ++ni)
#pragma unroll
                for (int mi = 0; mi < 2; ++mi)
                    mma16816(acc[mi][ni], ah[mi], &bl[ni >> 1][(ni & 1) * 2]);
#pragma unroll
            for (int ni = 0; ni < 8; ++ni)
#pragma unroll
                for (int mi = 0; mi < 2; ++mi)
                    mma16816(acc[mi][ni], al[mi], &bh[ni >> 1][(ni & 1) * 2]);
        }
        __syncthreads();
    }

    // epilogue
    const int gid = lane >> 2, tig = lane & 3;
#pragma unroll
    for (int mi = 0; mi < 2; ++mi) {
#pragma unroll
        for (int ni = 0; ni < 8; ++ni) {
            const int row = m0 + wm + mi * 16 + gid;
            const int col = n0 + wn + ni * 8 + 2 * tig;
            *(float2*)&C[(size_t)row * N + col] =
                make_float2(acc[mi][ni][0], acc[mi][ni][1]);
            *(float2*)&C[(size_t)(row + 8) * N + col] =
                make_float2(acc[mi][ni][2], acc[mi][ni][3]);
        }
    }
}

// ---------------- flash attention (fp32, causal, GQA) ----------------
#define QPITCH 132
#define KPITCH 132
#define VPITCH 68
#define PPITCH 68
__global__ void attn_kernel(const float* __restrict__ Q, const float* __restrict__ K,
                            const float* __restrict__ V, float* __restrict__ O,
                            int S, float scale) {
    extern __shared__ float smf[];
    float* Qs = smf;
    float* Ks = Qs + 128 * QPITCH;
    float* Vt = Ks + 64 * KPITCH;
    float* Ps = Vt + 128 * VPITCH;

    int qt = blockIdx.x, h = blockIdx.y, b = blockIdx.z;
    int kvh = h / (NH / NKV);
    int tid = threadIdx.x;
    int tx = tid & 7, ty = tid >> 3;
    int q0 = qt * 128;

    for (int it = tid; it < 128 * 32; it += 256) {
        int r = it >> 5, dq = (it & 31) * 4;
        float4 v = *(const float4*)(Q + ((size_t)(b * S + q0 + r) * NH + h) * HD + dq);
        float* dst = &Qs[r * QPITCH + dq];
        dst[0] = v.x; dst[1] = v.y; dst[2] = v.z; dst[3] = v.w;
    }

    float m_i[4], l_i[4], Of[4][16];
#pragma unroll
    for (int i = 0; i < 4; ++i) {
        m_i[i] = -3.0e38f; l_i[i] = 0.f;
#pragma unroll
        for (int j = 0; j < 16; ++j) Of[i][j] = 0.f;
    }

    int ntiles = (q0 + 128) / 64;
    for (int t = 0; t < ntiles; ++t) {
        int kv0 = t * 64;
        __syncthreads();
        for (int it = tid; it < 64 * 32; it += 256) {
            int c = it >> 5, dq = (it & 31) * 4;
            const float* kp = K + ((size_t)(b * S + kv0 + c) * NKV + kvh) * HD + dq;
            float4 kk = *(const float4*)kp;
            float* kd = &Ks[c * KPITCH + dq];
            kd[0] = kk.x; kd[1] = kk.y; kd[2] = kk.z; kd[3] = kk.w;
            const float* vp = V + ((size_t)(b * S + kv0 + c) * NKV + kvh) * HD + dq;
            float4 vv = *(const float4*)vp;
            Vt[(dq + 0) * VPITCH + c] = vv.x;
            Vt[(dq + 1) * VPITCH + c] = vv.y;
            Vt[(dq + 2) * VPITCH + c] = vv.z;
            Vt[(dq + 3) * VPITCH + c] = vv.w;
        }
        __syncthreads();

        float acc[4][8];
#pragma unroll
        for (int i = 0; i < 4; ++i)
#pragma unroll
            for (int j = 0; j < 8; ++j) acc[i][j] = 0.f;
#pragma unroll 4
        for (int k4 = 0; k4 < 32; ++k4) {
            float4 qa[4];
#pragma unroll
            for (int i = 0; i < 4; ++i)
                qa[i] = *(const float4*)&Qs[(ty * 4 + i) * QPITCH + k4 * 4];
#pragma unroll
            for (int j = 0; j < 8; ++j) {
                float4 kb = *(const float4*)&Ks[(tx + 8 * j) * KPITCH + k4 * 4];
#pragma unroll
                for (int i = 0; i < 4; ++i)
                    acc[i][j] += qa[i].x * kb.x + qa[i].y * kb.y
                               + qa[i].z * kb.z + qa[i].w * kb.w;
            }
        }

#pragma unroll
        for (int i = 0; i < 4; ++i) {
            int qi = q0 + ty * 4 + i;
            float mrow = -3.0e38f;
#pragma unroll
            for (int j = 0; j < 8; ++j) {
                int kidx = kv0 + tx + 8 * j;
                float sv = (kidx <= qi) ? acc[i][j] * scale : -1.0e30f;
                acc[i][j] = sv;
                mrow = fmaxf(mrow, sv);
            }
            mrow = fmaxf(mrow, __shfl_xor_sync(0xffffffffu, mrow, 1));
            mrow = fmaxf(mrow, __shfl_xor_sync(0xffffffffu, mrow, 2));
            mrow = fmaxf(mrow, __shfl_xor_sync(0xffffffffu, mrow, 4));
            float mnew  = fmaxf(m_i[i], mrow);
            float alpha = expf(m_i[i] - mnew);
            float lsum = 0.f;
#pragma unroll
            for (int j = 0; j < 8; ++j) {
                float p = expf(acc[i][j] - mnew);
                acc[i][j] = p;
                lsum += p;
            }
            lsum += __shfl_xor_sync(0xffffffffu, lsum, 1);
            lsum += __shfl_xor_sync(0xffffffffu, lsum, 2);
            lsum += __shfl_xor_sync(0xffffffffu, lsum, 4);
            l_i[i] = l_i[i] * alpha + lsum;
            m_i[i] = mnew;
#pragma unroll
            for (int j = 0; j < 16; ++j) Of[i][j] *= alpha;
#pragma unroll
            for (int j = 0; j < 8; ++j)
                Ps[(ty * 4 + i) * PPITCH + tx + 8 * j] = acc[i][j];
        }
        __syncthreads();

#pragma unroll 4
        for (int k4 = 0; k4 < 16; ++k4) {
            float4 pa[4];
#pragma unroll
            for (int i = 0; i < 4; ++i)
                pa[i] = *(const float4*)&Ps[(ty * 4 + i) * PPITCH + k4 * 4];
#pragma unroll
            for (int j = 0; j < 16; ++j) {
                float4 vb = *(const float4*)&Vt[(tx + 8 * j) * VPITCH + k4 * 4];
#pragma unroll
                for (int i = 0; i < 4; ++i)
                    Of[i][j] += pa[i].x * vb.x + pa[i].y * vb.y
                              + pa[i].z * vb.z + pa[i].w * vb.w;
            }
        }
    }

#pragma unroll
    for (int i = 0; i < 4; ++i) {
        int row = q0 + ty * 4 + i;
        float inv = 1.f / l_i[i];
        float* op = O + ((size_t)(b * S + row) * NH + h) * HD;
#pragma unroll
        for (int j = 0; j < 16; ++j)
            op[tx + 8 * j] = Of[i][j] * inv;
    }
}

// ---------------- launch ----------------
extern "C" void kernel_launch(void* const* d_in, const int* in_sizes, int n_in,
                              void* d_out, int out_size) {
    const float* hs  = (const float*)d_in[0];
    const float* wq  = (const float*)d_in[1];
    const float* wk  = (const float*)d_in[2];
    const float* wv  = (const float*)d_in[3];
    const float* wo  = (const float*)d_in[4];
    const int*   pos = (const int*)  d_in[6];

    int nnz = in_sizes[0] / HID;
    int b   = in_sizes[10] - 1;
    int s   = nnz / b;

    float *q, *kt, *vt, *kg, *vg, *attn;
    cudaGetSymbolAddress((void**)&q,    g_q);
    cudaGetSymbolAddress((void**)&kt,   g_kt);
    cudaGetSymbolAddress((void**)&vt,   g_vt);
    cudaGetSymbolAddress((void**)&kg,   g_kg);
    cudaGetSymbolAddress((void**)&vg,   g_vg);
    cudaGetSymbolAddress((void**)&attn, g_attn);

    __nv_bfloat16 *hsh, *hsl, *wqh, *wql, *wkh, *wkl, *wvh, *wvl, *woh, *wol, *ath, *atl;
    cudaGetSymbolAddress((void**)&hsh, g_hs_hi);
    cudaGetSymbolAddress((void**)&hsl, g_hs_lo);
    cudaGetSymbolAddress((void**)&wqh, g_wq_hi);
    cudaGetSymbolAddress((void**)&wql, g_wq_lo);
    cudaGetSymbolAddress((void**)&wkh, g_wk_hi);
    cudaGetSymbolAddress((void**)&wkl, g_wk_lo);
    cudaGetSymbolAddress((void**)&wvh, g_wv_hi);
    cudaGetSymbolAddress((void**)&wvl, g_wv_lo);
    cudaGetSymbolAddress((void**)&woh, g_wo_hi);
    cudaGetSymbolAddress((void**)&wol, g_wo_lo);
    cudaGetSymbolAddress((void**)&ath, g_at_hi);
    cudaGetSymbolAddress((void**)&atl, g_at_lo);

    const size_t ATTN_SMEM =
        (size_t)(128 * QPITCH + 64 * KPITCH + 128 * VPITCH + 128 * PPITCH) * sizeof(float);
    cudaFuncSetAttribute(attn_kernel, cudaFuncAttributeMaxDynamicSharedMemorySize,
                         (int)ATTN_SMEM);
    cudaFuncSetAttribute(hgemm_nt, cudaFuncAttributeMaxDynamicSharedMemorySize, GEMM_SMEM);

    // 1. RoPE cos/sin table
    rope_table_kernel<<<s, 64>>>();

    // 2. split-convert activations + weights to (bf16 hi, bf16 lo)
    {
        int n4;
        n4 = nnz * HID / 4;      cvt_split_kernel<<<(n4 + 255) / 256, 256>>>(hs, hsh, hsl, n4);
        n4 = NH  * HD * HID / 4; cvt_split_kernel<<<(n4 + 255) / 256, 256>>>(wq, wqh, wql, n4);
        n4 = NKV * HD * HID / 4; cvt_split_kernel<<<(n4 + 255) / 256, 256>>>(wk, wkh, wkl, n4);
        n4 = NKV * HD * HID / 4; cvt_split_kernel<<<(n4 + 255) / 256, 256>>>(wv, wvh, wvl, n4);
        n4 = HID * NH * HD / 4;  cvt_split_kernel<<<(n4 + 255) / 256, 256>>>(wo, woh, wol, n4);
    }

    // 3. projections (3xBF16 split HMMA GEMMs, pipelined)
    hgemm_nt<<<dim3((NH * HD) / BN,  nnz / BM), 256, GEMM_SMEM>>>(hsh, hsl, wqh, wql, q,  nnz, NH * HD,  HID);
    hgemm_nt<<<dim3((NKV * HD) / BN, nnz / BM), 256, GEMM_SMEM>>>(hsh, hsl, wkh, wkl, kt, nnz, NKV * HD, HID);
    hgemm_nt<<<dim3((NKV * HD) / BN, nnz / BM), 256, GEMM_SMEM>>>(hsh, hsl, wvh, wvl, vt, nnz, NKV * HD, HID);

    // 4. RoPE + paged-KV scatter (gathered order == position)
    rope_q_kernel<<<nnz, 256>>>(q, pos);
    ropekv_scatter_kernel<<<nnz, 256>>>(pos, s);

    // 5. causal GQA flash attention (fp32)
    float scale = 1.0f / sqrtf((float)HD);
    attn_kernel<<<dim3(s / 128, NH, b), 256, ATTN_SMEM>>>(q, kg, vg, attn, s, scale);

    // 6. output projection
    {
        int n4 = nnz * NH * HD / 4;
        cvt_split_kernel<<<(n4 + 255) / 256, 256>>>(attn, ath, atl, n4);
    }
    hgemm_nt<<<dim3(HID / BN, nnz / BM), 256, GEMM_SMEM>>>(ath, atl, woh, wol, (float*)d_out, nnz, HID, NH * HD);
}